// round 5
// baseline (speedup 1.0000x reference)
#include <cuda_runtime.h>
#include <cuda_fp16.h>
#include <cstdint>

// Problem constants
#define BATCH 128
#define TVIEW 196      // T
#define TTOT  392      // 2T
#define ENC   1024
#define DEC   512
#define NVIS  98       // V
#define NMASK 294      // M

#define MROWS (BATCH * NVIS)   // 12544

// Scratch
__device__ int g_rank[BATCH * TTOT];
__device__ int g_vis_tok[BATCH * NVIS];
__device__ __align__(16) __half g_xh[MROWS * ENC];   // 25.7 MB fp16 copy of x
__device__ __align__(16) __half g_wh[DEC * ENC];     // 1 MB fp16 copy of W

// ---------------------------------------------------------------------------
// helpers
// ---------------------------------------------------------------------------
__device__ __forceinline__ uint32_t smem_u32(const void* p) {
    uint32_t a;
    asm("{ .reg .u64 t; cvta.to.shared.u64 t, %1; cvt.u32.u64 %0, t; }" : "=r"(a) : "l"(p));
    return a;
}
__device__ __forceinline__ void cp_async16(uint32_t dst, const void* src) {
    asm volatile("cp.async.cg.shared.global [%0], [%1], 16;" :: "r"(dst), "l"(src) : "memory");
}
#define CP_COMMIT() asm volatile("cp.async.commit_group;" ::: "memory")
#define CP_WAIT(n)  asm volatile("cp.async.wait_group %0;" :: "n"(n) : "memory")

__device__ __forceinline__ void ldsm4(uint32_t* r, uint32_t addr) {
    asm volatile("ldmatrix.sync.aligned.m8n8.x4.shared.b16 {%0,%1,%2,%3}, [%4];"
                 : "=r"(r[0]), "=r"(r[1]), "=r"(r[2]), "=r"(r[3]) : "r"(addr));
}
__device__ __forceinline__ void mma16816(float* c, const uint32_t* a, const uint32_t* b) {
    asm volatile("mma.sync.aligned.m16n8k16.row.col.f32.f16.f16.f32 "
                 "{%0,%1,%2,%3}, {%4,%5,%6,%7}, {%8,%9}, {%0,%1,%2,%3};"
                 : "+f"(c[0]), "+f"(c[1]), "+f"(c[2]), "+f"(c[3])
                 : "r"(a[0]), "r"(a[1]), "r"(a[2]), "r"(a[3]), "r"(b[0]), "r"(b[1]));
}

// ---------------------------------------------------------------------------
// Kernel A: build visible-id index per batch row (dtype auto-detect).
// ---------------------------------------------------------------------------
__global__ void build_index_kernel(const void* __restrict__ mids_raw) {
    __shared__ int flags[TTOT];
    __shared__ int scanv[512];
    __shared__ int is64;

    const int b = blockIdx.x;
    const int t = threadIdx.x;

    if (t == 0) {
        const unsigned int* w = (const unsigned int*)mids_raw;
        int ok = 1;
        #pragma unroll 1
        for (int i = 0; i < 64; i++) {
            if (w[2 * i + 1] != 0u || w[2 * i] >= (unsigned)TTOT) { ok = 0; break; }
        }
        is64 = ok;
    }
    if (t < TTOT) flags[t] = 1;
    __syncthreads();

    if (is64) {
        const long long* m64 = (const long long*)mids_raw;
        for (int i = t; i < NMASK; i += blockDim.x)
            flags[(int)m64[(size_t)b * NMASK + i]] = 0;
    } else {
        const int* m32 = (const int*)mids_raw;
        for (int i = t; i < NMASK; i += blockDim.x)
            flags[m32[b * NMASK + i]] = 0;
    }
    __syncthreads();

    const int f = (t < TTOT) ? flags[t] : 0;
    scanv[t] = f;
    for (int off = 1; off < 512; off <<= 1) {
        __syncthreads();
        int v = scanv[t];
        int u = (t >= off) ? scanv[t - off] : 0;
        __syncthreads();
        scanv[t] = v + u;
    }
    __syncthreads();

    if (t < TTOT) {
        if (f) {
            int r = scanv[t] - 1;
            g_rank[b * TTOT + t] = r;
            g_vis_tok[b * NVIS + r] = t;
        } else {
            g_rank[b * TTOT + t] = -1;
        }
    }
}

// ---------------------------------------------------------------------------
// Kernel D: convert x and W to fp16 scratch (8 elems / thread).
// ---------------------------------------------------------------------------
#define XCH (MROWS * ENC / 8)    // 1605632 chunks of 8
#define WCH (DEC * ENC / 8)      // 65536
__global__ void convert_fp16_kernel(const float* __restrict__ x,
                                    const float* __restrict__ W) {
    const int i = blockIdx.x * blockDim.x + threadIdx.x;
    const float4* src;
    uint4* dst;
    int c;
    if (i < XCH) {
        src = (const float4*)x; dst = (uint4*)g_xh; c = i;
    } else if (i < XCH + WCH) {
        src = (const float4*)W; dst = (uint4*)g_wh; c = i - XCH;
    } else return;

    float4 v0 = src[2 * c], v1 = src[2 * c + 1];
    __half2 h0 = __float22half2_rn(make_float2(v0.x, v0.y));
    __half2 h1 = __float22half2_rn(make_float2(v0.z, v0.w));
    __half2 h2 = __float22half2_rn(make_float2(v1.x, v1.y));
    __half2 h3 = __float22half2_rn(make_float2(v1.z, v1.w));
    uint4 o;
    o.x = *(uint32_t*)&h0; o.y = *(uint32_t*)&h1;
    o.z = *(uint32_t*)&h2; o.w = *(uint32_t*)&h3;
    dst[c] = o;
}

// ---------------------------------------------------------------------------
// Kernel C: fill masked rows with mask_token + pos_embed + view_embed.
// ---------------------------------------------------------------------------
__global__ void fill_masked_kernel(const float* __restrict__ mask_token,
                                   const float* __restrict__ pos,
                                   const float* __restrict__ ve,
                                   float* __restrict__ out) {
    const int warp = (blockIdx.x * blockDim.x + threadIdx.x) >> 5;
    const int lane = threadIdx.x & 31;
    if (warp >= BATCH * TTOT) return;
    if (g_rank[warp] >= 0) return;

    const int t = warp % TTOT;
    const float4* mt = (const float4*)mask_token;
    const float4* pp = (const float4*)(pos + (size_t)t * DEC);
    const float4* vv = (const float4*)(ve + (size_t)(t >= TVIEW) * DEC);
    float4* o = (float4*)(out + (size_t)warp * DEC);

    #pragma unroll
    for (int j = 0; j < 4; j++) {
        int i = lane + j * 32;
        float4 a = mt[i], p = pp[i], c = vv[i];
        o[i] = make_float4(a.x + p.x + c.x, a.y + p.y + c.y,
                           a.z + p.z + c.z, a.w + p.w + c.w);
    }
}

// ---------------------------------------------------------------------------
// Kernel B: fp16 mma.sync GEMM (M=12544, N=512, K=1024), scatter epilogue.
// CTA 128x128, BK=64, 3-stage cp.async ring, 16 warps (4x4), warp tile 32x32.
// Register double-buffered ldmatrix fragments across the 4 k-steps per stage.
// ---------------------------------------------------------------------------
#define BK 64
#define NSTG 3
#define LDA 72                             // halfs per row (64 + 8 pad -> 144B rows)
#define STAGE_A_BYTES (128 * LDA * 2)      // 18432
#define STAGE_BYTES   (2 * STAGE_A_BYTES)  // A + B = 36864
#define SMEM_TOTAL (NSTG * STAGE_BYTES)    // 110592
#define LDC 132

__global__ void __launch_bounds__(512, 1)
gemm_scatter_mma(const float* __restrict__ bias,
                 const float* __restrict__ pos,
                 const float* __restrict__ ve,
                 float* __restrict__ out) {
    extern __shared__ char smem[];
    const uint32_t sbase = smem_u32(smem);

    const int tid  = threadIdx.x;
    const int wid  = tid >> 5;
    const int lane = tid & 31;
    const int wm = wid & 3;          // warp row (4)
    const int wn = wid >> 2;         // warp col (4)

    const int bn = blockIdx.x;       // 0..3  fast -> x L2 reuse
    const int bm = blockIdx.y;       // 0..97
    const int row0 = bm * 128;
    const int n0 = bn * 128;

    // cp.async mapping: each thread copies 2 adjacent 16B chunks of A and of B.
    // 128 rows x 8 chunks(16B) = 1024 chunks per tile; 512 threads x 2.
    const int car = tid >> 2;                 // 0..127 row
    const int cac = (tid & 3) * 2;            // chunk pair base 0,2,4,6
    const __half* srcA0 = g_xh + (size_t)(row0 + car) * ENC + cac * 8;
    const __half* srcB0 = g_wh + (size_t)(n0 + car) * ENC + cac * 8;
    const uint32_t dstOff = car * (LDA * 2) + cac * 16;

    // ldmatrix per-thread row/col (within stage tile)
    const int arow = wm * 32 + (lane & 15);
    const int acol = (lane >> 4) << 3;        // 0 or 8 halfs
    const int brow = wn * 32 + (lane & 7) + ((lane >> 4) << 3);
    const int bcol = ((lane >> 3) & 1) << 3;

    float acc[2][4][4];
    #pragma unroll
    for (int i = 0; i < 2; i++)
        #pragma unroll
        for (int j = 0; j < 4; j++)
            #pragma unroll
            for (int k = 0; k < 4; k++) acc[i][j][k] = 0.f;

    // prologue: stages 0,1
    #pragma unroll
    for (int s = 0; s < NSTG - 1; s++) {
        const uint32_t sa = sbase + s * STAGE_BYTES;
        cp_async16(sa + dstOff, srcA0 + s * BK);
        cp_async16(sa + dstOff + 16, srcA0 + s * BK + 8);
        cp_async16(sa + STAGE_A_BYTES + dstOff, srcB0 + s * BK);
        cp_async16(sa + STAGE_A_BYTES + dstOff + 16, srcB0 + s * BK + 8);
        CP_COMMIT();
    }

    uint32_t af[2][2][4], bf[2][2][4];

    #pragma unroll 1
    for (int s = 0; s < ENC / BK; s++) {
        CP_WAIT(1);
        __syncthreads();   // stage s ready; all warps done reading buf (s-1)%3

        // prefetch stage s+2 into buffer (s+2)%3 (== (s-1)%3, now free)
        if (s + 2 < ENC / BK) {
            const int sp = s + 2;
            const uint32_t sa = sbase + (sp % NSTG) * STAGE_BYTES;
            cp_async16(sa + dstOff, srcA0 + sp * BK);
            cp_async16(sa + dstOff + 16, srcA0 + sp * BK + 8);
            cp_async16(sa + STAGE_A_BYTES + dstOff, srcB0 + sp * BK);
            cp_async16(sa + STAGE_A_BYTES + dstOff + 16, srcB0 + sp * BK + 8);
        }
        CP_COMMIT();

        const uint32_t sa = sbase + (s % NSTG) * STAGE_BYTES;
        const uint32_t sb = sa + STAGE_A_BYTES;

        // preload k-step 0 fragments
        #pragma unroll
        for (int mt = 0; mt < 2; mt++)
            ldsm4(af[0][mt], sa + ((arow + mt * 16) * LDA + acol) * 2);
        #pragma unroll
        for (int p = 0; p < 2; p++)
            ldsm4(bf[0][p], sb + ((brow + p * 16) * LDA + bcol) * 2);

        #pragma unroll
        for (int ks = 0; ks < 4; ks++) {
            const int cur = ks & 1, nxt = cur ^ 1;
            if (ks < 3) {
                const int kc = (ks + 1) * 16;
                #pragma unroll
                for (int mt = 0; mt < 2; mt++)
                    ldsm4(af[nxt][mt], sa + ((arow + mt * 16) * LDA + kc + acol) * 2);
                #pragma unroll
                for (int p = 0; p < 2; p++)
                    ldsm4(bf[nxt][p], sb + ((brow + p * 16) * LDA + kc + bcol) * 2);
            }
            #pragma unroll
            for (int mt = 0; mt < 2; mt++)
                #pragma unroll
                for (int nt = 0; nt < 4; nt++)
                    mma16816(acc[mt][nt], af[cur][mt], &bf[cur][nt >> 1][(nt & 1) * 2]);
        }
    }

    __syncthreads();   // all ldmatrix done before overwriting smem with C

    // stage C to smem
    float* Cs = (float*)smem;
    const int g = lane >> 2, t2 = (lane & 3) * 2;
    #pragma unroll
    for (int mt = 0; mt < 2; mt++) {
        #pragma unroll
        for (int nt = 0; nt < 4; nt++) {
            const int r = wm * 32 + mt * 16 + g;
            const int c = wn * 32 + nt * 8 + t2;
            *(float2*)(Cs + r * LDC + c) = make_float2(acc[mt][nt][0], acc[mt][nt][1]);
            *(float2*)(Cs + (r + 8) * LDC + c) = make_float2(acc[mt][nt][2], acc[mt][nt][3]);
        }
    }
    __syncthreads();

    // scatter rows: warp w -> rows w*8 .. w*8+7, lane covers 128 cols (float4)
    const int col = lane * 4;
    const float4 bb = *(const float4*)(bias + n0 + col);
    #pragma unroll
    for (int i = 0; i < 8; i++) {
        const int r = wid * 8 + i;
        const int mrow = row0 + r;
        const int b = mrow / NVIS;
        const int tok = g_vis_tok[mrow];
        const int viewi = (tok >= TVIEW);
        float4 c = *(float4*)(Cs + r * LDC + col);
        float4 p = *(const float4*)(pos + (size_t)tok * DEC + n0 + col);
        float4 v = *(const float4*)(ve + (size_t)viewi * DEC + n0 + col);
        float4 o;
        o.x = c.x + p.x + v.x + bb.x;
        o.y = c.y + p.y + v.y + bb.y;
        o.z = c.z + p.z + v.z + bb.z;
        o.w = c.w + p.w + v.w + bb.w;
        *(float4*)(out + ((size_t)(b * TTOT + tok)) * DEC + n0 + col) = o;
    }
}

// ---------------------------------------------------------------------------
extern "C" void kernel_launch(void* const* d_in, const int* in_sizes, int n_in,
                              void* d_out, int out_size) {
    const float* x          = (const float*)d_in[0];
    const void*  mids       = d_in[1];
    const float* W          = (const float*)d_in[2];
    const float* bias       = (const float*)d_in[3];
    const float* mask_token = (const float*)d_in[4];
    const float* pos        = (const float*)d_in[5];
    const float* ve         = (const float*)d_in[6];
    float* out = (float*)d_out;

    // fp16 conversion of x and W
    {
        const int total = XCH + WCH;
        convert_fp16_kernel<<<(total + 255) / 256, 256>>>(x, W);
    }

    build_index_kernel<<<BATCH, 512>>>(mids);

    {
        const int nwarps = BATCH * TTOT;
        const int threads = 256;
        const int blocks = (nwarps * 32 + threads - 1) / threads;
        fill_masked_kernel<<<blocks, threads>>>(mask_token, pos, ve, out);
    }

    {
        cudaFuncSetAttribute(gemm_scatter_mma,
                             cudaFuncAttributeMaxDynamicSharedMemorySize, SMEM_TOTAL);
        dim3 grid(4, 98);
        gemm_scatter_mma<<<grid, 512, SMEM_TOTAL>>>(bias, pos, ve, out);
    }
}